// round 2
// baseline (speedup 1.0000x reference)
#include <cuda_runtime.h>
#include <math.h>

// Quantized weights, produced by prep_kernel each launch (deterministic).
__device__ float g_qw1[36];     // [4][1][3][3]
__device__ float g_qw2[144];    // [4][4][3][3]
__device__ float g_qwf[1960];   // [10][196]

// ---------------------------------------------------------------------------
// Prep: compute per-tensor max|w|, fake-quantize to ternary {-s,0,s}.
// ---------------------------------------------------------------------------
__global__ void prep_kernel(const float* __restrict__ w1,
                            const float* __restrict__ w2,
                            const float* __restrict__ wf) {
    __shared__ float red[256];
    __shared__ float scales[3];
    int t = threadIdx.x;
    const float* srcs[3] = {w1, w2, wf};
    const int    ns[3]   = {36, 144, 1960};
    for (int j = 0; j < 3; j++) {
        float m = 0.f;
        for (int i = t; i < ns[j]; i += 256) m = fmaxf(m, fabsf(srcs[j][i]));
        red[t] = m;
        __syncthreads();
        for (int s = 128; s > 0; s >>= 1) {
            if (t < s) red[t] = fmaxf(red[t], red[t + s]);
            __syncthreads();
        }
        if (t == 0) scales[j] = red[0];
        __syncthreads();
    }
    float s1 = scales[0], s2 = scales[1], sf = scales[2];
    for (int i = t; i < 36; i += 256) {
        float r = rintf(w1[i] / s1); r = fminf(fmaxf(r, -1.f), 1.f);
        g_qw1[i] = r * s1;
    }
    for (int i = t; i < 144; i += 256) {
        float r = rintf(w2[i] / s2); r = fminf(fmaxf(r, -1.f), 1.f);
        g_qw2[i] = r * s2;
    }
    for (int i = t; i < 1960; i += 256) {
        float r = rintf(wf[i] / sf); r = fminf(fmaxf(r, -1.f), 1.f);
        g_qwf[i] = r * sf;
    }
}

// quant_relu_2bit, applied AFTER maxpool (monotone ops commute with max)
__device__ __forceinline__ float quant_relu(float v) {
    return rintf(fminf(fmaxf(v, 0.f), 6.f) * 0.5f) * 2.0f;
}

// ---------------------------------------------------------------------------
// Fused per-image kernel: block b = image b, 128 threads.
//   conv1(28x28, 1->4) + qrelu + pool -> conv2(14x14, 4->4) + qrelu + pool
//   -> FC 196->10
// ---------------------------------------------------------------------------
__global__ __launch_bounds__(128, 8)
void fused_kernel(const float* __restrict__ x, float* __restrict__ out) {
    __shared__ float s_in[30 * 30];        // padded 28x28 input
    __shared__ float s_p1[4 * 16 * 16];    // padded 4 x 14x14 pooled stage-1
    __shared__ float s_p2[196];            // 4 x 7x7 pooled stage-2 (flatten order)
    __shared__ float s_w1[36];
    __shared__ float s_w2[144];
    __shared__ float s_wf[1960];

    const int t = threadIdx.x;
    const int b = blockIdx.x;

    // Stage 0: weights to smem + zero padded tiles
    for (int i = t; i < 36;   i += 128) s_w1[i] = g_qw1[i];
    for (int i = t; i < 144;  i += 128) s_w2[i] = g_qw2[i];
    for (int i = t; i < 1960; i += 128) s_wf[i] = g_qwf[i];
    for (int i = t; i < 900;  i += 128) s_in[i] = 0.f;
    for (int i = t; i < 1024; i += 128) s_p1[i] = 0.f;
    __syncthreads();

    // Load 28x28 input into interior of 30x30
    const float* xin = x + (size_t)b * 784;
    for (int i = t; i < 784; i += 128) {
        int y = i / 28, xx = i % 28;
        s_in[(y + 1) * 30 + (xx + 1)] = xin[i];
    }
    __syncthreads();

    // Stage 1: conv1 + (pool then quant). p indexes pooled output [4][14][14].
    for (int p = t; p < 784; p += 128) {
        int c = p / 196, rem = p % 196;
        int py = rem / 14, px = rem % 14;
        const float* wc = s_w1 + c * 9;
        float k0 = wc[0], k1 = wc[1], k2 = wc[2],
              k3 = wc[3], k4 = wc[4], k5 = wc[5],
              k6 = wc[6], k7 = wc[7], k8 = wc[8];
        float m = -1e30f;
        #pragma unroll
        for (int dy = 0; dy < 2; dy++) {
            #pragma unroll
            for (int dx = 0; dx < 2; dx++) {
                const float* p0 = s_in + (2 * py + dy) * 30 + (2 * px + dx);
                float v = p0[0]  * k0 + p0[1]  * k1 + p0[2]  * k2
                        + p0[30] * k3 + p0[31] * k4 + p0[32] * k5
                        + p0[60] * k6 + p0[61] * k7 + p0[62] * k8;
                m = fmaxf(m, v);
            }
        }
        s_p1[c * 256 + (py + 1) * 16 + (px + 1)] = quant_relu(m);
    }
    __syncthreads();

    // Stage 2: conv2 + (pool then quant). p indexes pooled output [4][7][7].
    for (int p = t; p < 196; p += 128) {
        int c = p / 49, rem = p % 49;
        int py = rem / 7, px = rem % 7;
        float m = -1e30f;
        #pragma unroll
        for (int dy = 0; dy < 2; dy++) {
            #pragma unroll
            for (int dx = 0; dx < 2; dx++) {
                int y = 2 * py + dy, xx = 2 * px + dx;
                float v = 0.f;
                #pragma unroll
                for (int ci = 0; ci < 4; ci++) {
                    const float* p0 = s_p1 + ci * 256 + y * 16 + xx;
                    const float* wc = s_w2 + (c * 4 + ci) * 9;
                    v += p0[0]  * wc[0] + p0[1]  * wc[1] + p0[2]  * wc[2]
                       + p0[16] * wc[3] + p0[17] * wc[4] + p0[18] * wc[5]
                       + p0[32] * wc[6] + p0[33] * wc[7] + p0[34] * wc[8];
                }
                m = fmaxf(m, v);
            }
        }
        s_p2[p] = quant_relu(m);  // flatten order c*49 + py*7 + px
    }
    __syncthreads();

    // Stage 3: FC 196 -> 10 (threads 0..9, 4 accumulators to break latency)
    if (t < 10) {
        const float* wrow = s_wf + t * 196;
        float a0 = 0.f, a1 = 0.f, a2 = 0.f, a3 = 0.f;
        #pragma unroll 7
        for (int k = 0; k < 196; k += 4) {
            a0 += s_p2[k]     * wrow[k];
            a1 += s_p2[k + 1] * wrow[k + 1];
            a2 += s_p2[k + 2] * wrow[k + 2];
            a3 += s_p2[k + 3] * wrow[k + 3];
        }
        out[(size_t)b * 10 + t] = (a0 + a1) + (a2 + a3);
    }
}

extern "C" void kernel_launch(void* const* d_in, const int* in_sizes, int n_in,
                              void* d_out, int out_size) {
    const float* x  = (const float*)d_in[0];
    const float* w1 = (const float*)d_in[1];
    const float* w2 = (const float*)d_in[2];
    const float* wf = (const float*)d_in[3];
    float* out = (float*)d_out;
    int B = in_sizes[0] / 784;

    prep_kernel<<<1, 256>>>(w1, w2, wf);
    fused_kernel<<<B, 128>>>(x, out);
}

// round 3
// speedup vs baseline: 2.6240x; 2.6240x over previous
#include <cuda_runtime.h>
#include <math.h>

// Prep outputs (written each launch, deterministic)
__device__ float g_qw1[36];     // fake-quantized conv1 weights [4][9]
__device__ int   g_w2p[36];     // conv2 int weights packed: [oc][k], byte ci = wint[oc][ci][k]
__device__ int   g_wfp[490];    // FC int weights packed: [o][j], byte ci = wint[o][ci*49+j]
__device__ float g_scales[2];   // {2*s2, 2*sf}

__device__ __forceinline__ int qclip(float w, float s) {
    float r = rintf(w / s);
    r = fminf(fmaxf(r, -1.f), 1.f);
    return (int)r;
}

__global__ void prep_kernel(const float* __restrict__ w1,
                            const float* __restrict__ w2,
                            const float* __restrict__ wf) {
    __shared__ float red[256];
    __shared__ float scales[3];
    int t = threadIdx.x;
    const float* srcs[3] = {w1, w2, wf};
    const int    ns[3]   = {36, 144, 1960};
    for (int j = 0; j < 3; j++) {
        float m = 0.f;
        for (int i = t; i < ns[j]; i += 256) m = fmaxf(m, fabsf(srcs[j][i]));
        red[t] = m;
        __syncthreads();
        for (int s = 128; s > 0; s >>= 1) {
            if (t < s) red[t] = fmaxf(red[t], red[t + s]);
            __syncthreads();
        }
        if (t == 0) scales[j] = red[0];
        __syncthreads();
    }
    float s1 = scales[0], s2 = scales[1], sf = scales[2];

    // conv1: fake-quantized float weights
    if (t < 36) {
        g_qw1[t] = (float)qclip(w1[t], s1) * s1;
    }
    // conv2: packed int8x4 along input channel. w2 layout [oc][ci][3][3]
    if (t < 36) {
        int oc = t / 9, k = t % 9;
        int packed = 0;
        #pragma unroll
        for (int ci = 0; ci < 4; ci++) {
            int q = qclip(w2[(oc * 4 + ci) * 9 + k], s2);
            packed |= (q & 0xFF) << (8 * ci);
        }
        g_w2p[t] = packed;
    }
    // FC: packed int8x4 along channel (k = ci*49 + j). wf layout [10][196]
    for (int i = t; i < 490; i += 256) {
        int o = i / 49, j = i % 49;
        int packed = 0;
        #pragma unroll
        for (int ci = 0; ci < 4; ci++) {
            int q = qclip(wf[o * 196 + ci * 49 + j], sf);
            packed |= (q & 0xFF) << (8 * ci);
        }
        g_wfp[i] = packed;
    }
    if (t == 0) { g_scales[0] = 2.f * s2; g_scales[1] = 2.f * sf; }
}

// ---------------------------------------------------------------------------
// Fused per-image kernel, 128 threads per image.
// ---------------------------------------------------------------------------
__global__ __launch_bounds__(128)
void fused_kernel(const float* __restrict__ x, float* __restrict__ out) {
    __shared__ __align__(16) float s_in[900];   // padded 30x30 input
    __shared__ __align__(16) int   s_p1[256];   // padded 16x16, int8x4 acts {0..3}
    __shared__ int   s_p2p[49];                 // 7x7, int8x4 acts {0..3}
    __shared__ __align__(16) float s_w1[36];
    __shared__ int   s_w2p[36];
    __shared__ float s_sc[2];

    const int t = threadIdx.x;
    const int b = blockIdx.x;
    const int lane = t & 31;
    const int wrp  = t >> 5;

    // ---- Phase A: stage weights, zero pads, load input (float4) ----
    if (t < 36) { s_w1[t] = g_qw1[t]; s_w2p[t] = g_w2p[t]; }
    if (t < 2)  { s_sc[t] = g_scales[t]; }
    s_p1[t] = 0; s_p1[t + 128] = 0;
    if (t < 116) {  // border of 30x30
        int r, c;
        if (t < 30)      { r = 0;       c = t;       }
        else if (t < 60) { r = 29;      c = t - 30;  }
        else if (t < 88) { r = t - 59;  c = 0;       }
        else             { r = t - 87;  c = 29;      }
        s_in[r * 30 + c] = 0.f;
    }
    {
        const float4* xv = (const float4*)(x + (size_t)b * 784);
        #pragma unroll
        for (int it = 0; it < 2; it++) {
            int idx = t + it * 128;
            if (idx < 196) {
                float4 v = xv[idx];
                int y = idx / 7, c0 = (idx % 7) * 4;
                float* dst = s_in + (y + 1) * 30 + c0 + 1;
                dst[0] = v.x; dst[1] = v.y; dst[2] = v.z; dst[3] = v.w;
            }
        }
    }
    __syncthreads();

    // ---- Phase B: conv1 + pool + quant. One thread = one pooled pixel, all 4 ch.
    {
        float wr[36];
        #pragma unroll
        for (int i = 0; i < 9; i++) {
            float4 v = ((const float4*)s_w1)[i];
            wr[4*i] = v.x; wr[4*i+1] = v.y; wr[4*i+2] = v.z; wr[4*i+3] = v.w;
        }
        #pragma unroll
        for (int it = 0; it < 2; it++) {
            int p = t + it * 128;
            if (p < 196) {
                int py = p / 14, px = p - py * 14;
                const float* bp = s_in + py * 60 + px * 2;  // 4x4 patch top-left
                float r[16];
                #pragma unroll
                for (int i = 0; i < 4; i++) {
                    float2 a = *(const float2*)(bp + 30 * i);
                    float2 c = *(const float2*)(bp + 30 * i + 2);
                    r[4*i] = a.x; r[4*i+1] = a.y; r[4*i+2] = c.x; r[4*i+3] = c.y;
                }
                int packed = 0;
                #pragma unroll
                for (int ch = 0; ch < 4; ch++) {
                    const float* w = wr + ch * 9;
                    float m = -1e30f;
                    #pragma unroll
                    for (int dy = 0; dy < 2; dy++) {
                        #pragma unroll
                        for (int dx = 0; dx < 2; dx++) {
                            float v = r[dy*4+dx]     * w[0] + r[dy*4+dx+1]     * w[1] + r[dy*4+dx+2]     * w[2]
                                    + r[(dy+1)*4+dx] * w[3] + r[(dy+1)*4+dx+1] * w[4] + r[(dy+1)*4+dx+2] * w[5]
                                    + r[(dy+2)*4+dx] * w[6] + r[(dy+2)*4+dx+1] * w[7] + r[(dy+2)*4+dx+2] * w[8];
                            m = fmaxf(m, v);
                        }
                    }
                    // act = 2*q, q in {0,1,2,3}; store q
                    int q = (int)rintf(fminf(fmaxf(m, 0.f), 6.f) * 0.5f);
                    packed |= q << (8 * ch);
                }
                s_p1[(py + 1) * 16 + px + 1] = packed;
            }
        }
    }
    __syncthreads();

    // ---- Phase C: conv2 (int dp4a) + pool + quant. warp = out-channel, lane = pixel.
    {
        const float hs2 = s_sc[0];  // 2*s2
        const int oc = wrp;
        int wq[9];
        #pragma unroll
        for (int k = 0; k < 9; k++) wq[k] = s_w2p[oc * 9 + k];
        #pragma unroll
        for (int it = 0; it < 2; it++) {
            int pix = lane + it * 32;
            if (pix < 49) {
                int py = pix / 7, px = pix - py * 7;
                const int* bp = s_p1 + py * 32 + px * 2;  // 4x4 int patch
                int a[16];
                #pragma unroll
                for (int i = 0; i < 4; i++) {
                    int2 u = *(const int2*)(bp + 16 * i);
                    int2 v = *(const int2*)(bp + 16 * i + 2);
                    a[4*i] = u.x; a[4*i+1] = u.y; a[4*i+2] = v.x; a[4*i+3] = v.y;
                }
                int mbest = -1000000;
                #pragma unroll
                for (int dy = 0; dy < 2; dy++) {
                    #pragma unroll
                    for (int dx = 0; dx < 2; dx++) {
                        int s = 0;
                        #pragma unroll
                        for (int ky = 0; ky < 3; ky++)
                            #pragma unroll
                            for (int kx = 0; kx < 3; kx++)
                                s = __dp4a(a[(dy + ky) * 4 + dx + kx], wq[ky * 3 + kx], s);
                        mbest = max(mbest, s);
                    }
                }
                // conv value = hs2 * mbest (acts were 2q); quantize, store q2 byte
                int q = (int)rintf(fminf(fmaxf(hs2 * (float)mbest, 0.f), 6.f) * 0.5f);
                ((unsigned char*)s_p2p)[pix * 4 + oc] = (unsigned char)q;
            }
        }
    }
    __syncthreads();

    // ---- Phase D: FC 196->10 via dp4a, warp-per-output(s), shuffle reduce.
    {
        const float hsf = s_sc[1];  // 2*sf
        for (int o = wrp; o < 10; o += 4) {
            const int* wrow = g_wfp + o * 49;
            int s = __dp4a(s_p2p[lane], __ldg(wrow + lane), 0);
            if (lane < 17)
                s = __dp4a(s_p2p[32 + lane], __ldg(wrow + 32 + lane), s);
            #pragma unroll
            for (int off = 16; off; off >>= 1)
                s += __shfl_xor_sync(0xffffffffu, s, off);
            if (lane == 0)
                out[(size_t)b * 10 + o] = hsf * (float)s;
        }
    }
}

extern "C" void kernel_launch(void* const* d_in, const int* in_sizes, int n_in,
                              void* d_out, int out_size) {
    const float* x  = (const float*)d_in[0];
    const float* w1 = (const float*)d_in[1];
    const float* w2 = (const float*)d_in[2];
    const float* wf = (const float*)d_in[3];
    float* out = (float*)d_out;
    int B = in_sizes[0] / 784;

    prep_kernel<<<1, 256>>>(w1, w2, wf);
    fused_kernel<<<B, 128>>>(x, out);
}

// round 4
// speedup vs baseline: 2.9520x; 1.1250x over previous
#include <cuda_runtime.h>
#include <math.h>

// Prep outputs (written each launch, deterministic)
__device__ float g_qw1t[36];    // conv1 fake-quant weights, TRANSPOSED [k][ch] (k=0..8, ch=0..3)
__device__ int   g_w2p2[36];    // conv2 packed ints, layout [ocp][k][c]: idx=ocp*18+k*2+c, byte ci
__device__ int   g_wfp[490];    // FC packed ints: [o][j], byte ci = q(wf[o][ci*49+j])
__device__ float g_scales[2];   // {2*s2, 2*sf}

__device__ __forceinline__ int qclip(float w, float s) {
    float r = rintf(w / s);
    r = fminf(fmaxf(r, -1.f), 1.f);
    return (int)r;
}

__global__ void prep_kernel(const float* __restrict__ w1,
                            const float* __restrict__ w2,
                            const float* __restrict__ wf) {
    __shared__ float red[256];
    __shared__ float scales[3];
    int t = threadIdx.x;
    const float* srcs[3] = {w1, w2, wf};
    const int    ns[3]   = {36, 144, 1960};
    for (int j = 0; j < 3; j++) {
        float m = 0.f;
        for (int i = t; i < ns[j]; i += 256) m = fmaxf(m, fabsf(srcs[j][i]));
        red[t] = m;
        __syncthreads();
        for (int s = 128; s > 0; s >>= 1) {
            if (t < s) red[t] = fmaxf(red[t], red[t + s]);
            __syncthreads();
        }
        if (t == 0) scales[j] = red[0];
        __syncthreads();
    }
    float s1 = scales[0], s2 = scales[1], sf = scales[2];

    // conv1 transposed: entry t = k*4+ch
    if (t < 36) {
        int ch = t & 3, k = t >> 2;
        g_qw1t[t] = (float)qclip(w1[ch * 9 + k], s1) * s1;
    }
    // conv2: [ocp][k][c], oc = 2*ocp + c, bytes over ci
    if (t < 36) {
        int ocp = t / 18, r = t % 18, k = r >> 1, c = r & 1;
        int oc = 2 * ocp + c;
        int packed = 0;
        #pragma unroll
        for (int ci = 0; ci < 4; ci++) {
            int q = qclip(w2[(oc * 4 + ci) * 9 + k], s2);
            packed |= (q & 0xFF) << (8 * ci);
        }
        g_w2p2[t] = packed;
    }
    // FC packed along channel
    for (int i = t; i < 490; i += 256) {
        int o = i / 49, j = i % 49;
        int packed = 0;
        #pragma unroll
        for (int ci = 0; ci < 4; ci++) {
            int q = qclip(wf[o * 196 + ci * 49 + j], sf);
            packed |= (q & 0xFF) << (8 * ci);
        }
        g_wfp[i] = packed;
    }
    if (t == 0) { g_scales[0] = 2.f * s2; g_scales[1] = 2.f * sf; }
}

// ---- f32x2 packed helpers ----
typedef unsigned long long ull;
__device__ __forceinline__ ull pk2(float a, float b) {
    ull r; asm("mov.b64 %0, {%1, %2};" : "=l"(r) : "f"(a), "f"(b)); return r;
}
__device__ __forceinline__ ull dup2(float a) {
    ull r; asm("mov.b64 %0, {%1, %1};" : "=l"(r) : "f"(a)); return r;
}
__device__ __forceinline__ void ffma2(ull& d, ull a, ull b) {
    asm("fma.rn.f32x2 %0, %1, %2, %0;" : "+l"(d) : "l"(a), "l"(b));
}
__device__ __forceinline__ void unpk2(ull v, float& lo, float& hi) {
    asm("mov.b64 {%0, %1}, %2;" : "=f"(lo), "=f"(hi) : "l"(v));
}

__device__ __forceinline__ int quant2b(float v) {
    // round(clip(v,0,6)/2) in {0..3}:  min in float, round, max in int
    return max(__float2int_rn(fminf(v, 6.f) * 0.5f), 0);
}

// ---------------------------------------------------------------------------
// Fused per-image kernel: block = image, 128 threads.
// ---------------------------------------------------------------------------
__global__ __launch_bounds__(128, 6)
void fused_kernel(const float* __restrict__ x, float* __restrict__ out) {
    __shared__ __align__(16) float s_in[900];   // padded 30x30 input
    __shared__ __align__(16) int   s_p1[256];   // padded 16x16, int8x4 acts {0..3}
    __shared__ __align__(8)  int   s_p2p[49];   // 7x7, int8x4 acts {0..3}
    __shared__ __align__(16) float s_w1[36];    // transposed [k][ch]
    __shared__ __align__(8)  int   s_w2p[36];
    __shared__ float s_sc[2];

    const int t = threadIdx.x;
    const int b = blockIdx.x;
    const int lane = t & 31;
    const int wrp  = t >> 5;

    // ---- Phase A: stage weights, zero pads, load input ----
    if (t < 36) { s_w1[t] = g_qw1t[t]; s_w2p[t] = g_w2p2[t]; }
    if (t < 2)  { s_sc[t] = g_scales[t]; }
    s_p1[t] = 0; s_p1[t + 128] = 0;
    if (t < 116) {  // border of 30x30
        int r, c;
        if (t < 30)      { r = 0;       c = t;       }
        else if (t < 60) { r = 29;      c = t - 30;  }
        else if (t < 88) { r = t - 59;  c = 0;       }
        else             { r = t - 87;  c = 29;      }
        s_in[r * 30 + c] = 0.f;
    }
    {
        const float4* xv = (const float4*)(x + (size_t)b * 784);
        #pragma unroll
        for (int it = 0; it < 2; it++) {
            int idx = t + it * 128;
            if (idx < 196) {
                float4 v = xv[idx];
                int y = idx / 7, c0 = (idx % 7) * 4;
                float* dst = s_in + (y + 1) * 30 + c0 + 1;
                dst[0] = v.x; dst[1] = v.y; dst[2] = v.z; dst[3] = v.w;
            }
        }
    }
    __syncthreads();

    // ---- Phase B: conv1 + pool + quant with packed f32x2 (channel pairs) ----
    {
        // weight pairs: w01[k]=(w_ch0[k],w_ch1[k]), w23[k]=(w_ch2[k],w_ch3[k])
        ull w01[9], w23[9];
        #pragma unroll
        for (int k = 0; k < 9; k++) {
            float4 v = ((const float4*)s_w1)[k];
            w01[k] = pk2(v.x, v.y);
            w23[k] = pk2(v.z, v.w);
        }
        #pragma unroll
        for (int it = 0; it < 2; it++) {
            int p = t + it * 128;
            if (p < 196) {
                int py = p / 14, px = p - py * 14;
                const float* bp = s_in + py * 60 + px * 2;  // 4x4 patch top-left
                ull a01[4] = {0, 0, 0, 0};  // windows w=dy*2+dx, (ch0,ch1)
                ull a23[4] = {0, 0, 0, 0};  // (ch2,ch3)
                #pragma unroll
                for (int row = 0; row < 4; row++) {
                    float2 u = *(const float2*)(bp + 30 * row);
                    float2 v = *(const float2*)(bp + 30 * row + 2);
                    ull d0 = dup2(u.x), d1 = dup2(u.y), d2 = dup2(v.x), d3 = dup2(v.y);
                    #pragma unroll
                    for (int dy = 0; dy < 2; dy++) {
                        int kr = row - dy;
                        if (kr >= 0 && kr <= 2) {
                            // win dx=0: taps d0,d1,d2 ; win dx=1: taps d1,d2,d3
                            ffma2(a01[dy * 2 + 0], d0, w01[kr * 3 + 0]);
                            ffma2(a01[dy * 2 + 0], d1, w01[kr * 3 + 1]);
                            ffma2(a01[dy * 2 + 0], d2, w01[kr * 3 + 2]);
                            ffma2(a01[dy * 2 + 1], d1, w01[kr * 3 + 0]);
                            ffma2(a01[dy * 2 + 1], d2, w01[kr * 3 + 1]);
                            ffma2(a01[dy * 2 + 1], d3, w01[kr * 3 + 2]);
                            ffma2(a23[dy * 2 + 0], d0, w23[kr * 3 + 0]);
                            ffma2(a23[dy * 2 + 0], d1, w23[kr * 3 + 1]);
                            ffma2(a23[dy * 2 + 0], d2, w23[kr * 3 + 2]);
                            ffma2(a23[dy * 2 + 1], d1, w23[kr * 3 + 0]);
                            ffma2(a23[dy * 2 + 1], d2, w23[kr * 3 + 1]);
                            ffma2(a23[dy * 2 + 1], d3, w23[kr * 3 + 2]);
                        }
                    }
                }
                // max over 4 windows per channel, then quantize
                float m0 = -1e30f, m1 = -1e30f, m2 = -1e30f, m3 = -1e30f;
                #pragma unroll
                for (int w = 0; w < 4; w++) {
                    float c0, c1, c2, c3;
                    unpk2(a01[w], c0, c1);
                    unpk2(a23[w], c2, c3);
                    m0 = fmaxf(m0, c0); m1 = fmaxf(m1, c1);
                    m2 = fmaxf(m2, c2); m3 = fmaxf(m3, c3);
                }
                int q0 = quant2b(m0), q1 = quant2b(m1),
                    q2 = quant2b(m2), q3 = quant2b(m3);
                s_p1[(py + 1) * 16 + px + 1] = q0 | (q1 << 8) | (q2 << 16) | (q3 << 24);
            }
        }
    }
    __syncthreads();

    // ---- Phase C: conv2 via dp4a. Thread = (pixel, oc-pair). 98 active. ----
    if (t < 98) {
        const float hs2 = s_sc[0];  // 2*s2
        int pix = t >> 1, ocp = t & 1;
        int py = pix / 7, px = pix - py * 7;
        const int* bp = s_p1 + py * 32 + px * 2;  // 4x4 int patch
        int a[16];
        #pragma unroll
        for (int i = 0; i < 4; i++) {
            int2 u = *(const int2*)(bp + 16 * i);
            int2 v = *(const int2*)(bp + 16 * i + 2);
            a[4*i] = u.x; a[4*i+1] = u.y; a[4*i+2] = v.x; a[4*i+3] = v.y;
        }
        int wq0[9], wq1[9];
        #pragma unroll
        for (int k = 0; k < 9; k++) {
            int2 wv = ((const int2*)(s_w2p + ocp * 18))[k];
            wq0[k] = wv.x; wq1[k] = wv.y;
        }
        int m0 = -1000000, m1 = -1000000;
        #pragma unroll
        for (int dy = 0; dy < 2; dy++) {
            #pragma unroll
            for (int dx = 0; dx < 2; dx++) {
                int s0 = 0, s1 = 0;
                #pragma unroll
                for (int ky = 0; ky < 3; ky++) {
                    #pragma unroll
                    for (int kx = 0; kx < 3; kx++) {
                        int av = a[(dy + ky) * 4 + dx + kx];
                        s0 = __dp4a(av, wq0[ky * 3 + kx], s0);
                        s1 = __dp4a(av, wq1[ky * 3 + kx], s1);
                    }
                }
                m0 = max(m0, s0); m1 = max(m1, s1);
            }
        }
        int q0 = quant2b(hs2 * (float)m0);
        int q1 = quant2b(hs2 * (float)m1);
        ((unsigned short*)s_p2p)[pix * 2 + ocp] =
            (unsigned short)(q0 | (q1 << 8));
    }
    __syncthreads();

    // ---- Phase D: FC 196->10 via dp4a, warp-per-output, shuffle reduce ----
    {
        const float hsf = s_sc[1];  // 2*sf
        for (int o = wrp; o < 10; o += 4) {
            const int* wrow = g_wfp + o * 49;
            int s = __dp4a(s_p2p[lane], __ldg(wrow + lane), 0);
            if (lane < 17)
                s = __dp4a(s_p2p[32 + lane], __ldg(wrow + 32 + lane), s);
            #pragma unroll
            for (int off = 16; off; off >>= 1)
                s += __shfl_xor_sync(0xffffffffu, s, off);
            if (lane == 0)
                out[(size_t)b * 10 + o] = hsf * (float)s;
        }
    }
}

extern "C" void kernel_launch(void* const* d_in, const int* in_sizes, int n_in,
                              void* d_out, int out_size) {
    const float* x  = (const float*)d_in[0];
    const float* w1 = (const float*)d_in[1];
    const float* w2 = (const float*)d_in[2];
    const float* wf = (const float*)d_in[3];
    float* out = (float*)d_out;
    int B = in_sizes[0] / 784;

    prep_kernel<<<1, 256>>>(w1, w2, wf);
    fused_kernel<<<B, 128>>>(x, out);
}

// round 5
// speedup vs baseline: 3.8482x; 1.3036x over previous
#include <cuda_runtime.h>
#include <math.h>

// Prep outputs (written each launch, deterministic)
__device__ __align__(16) float g_qw1t[36];  // conv1 fq weights TRANSPOSED [k][ch]
__device__ __align__(8)  int   g_w2p2[36];  // conv2 packed: [ocp][k][c], byte ci
__device__ int   g_wfp[528];                // FC packed [o][j] byte ci; padded, tail zero
__device__ float g_scales[2];               // {2*s2, 2*sf}

__device__ __forceinline__ int qclip(float w, float s) {
    float r = rintf(w / s);
    r = fminf(fmaxf(r, -1.f), 1.f);
    return (int)r;
}

__global__ void prep_kernel(const float* __restrict__ w1,
                            const float* __restrict__ w2,
                            const float* __restrict__ wf) {
    __shared__ float red[256];
    __shared__ float scales[3];
    int t = threadIdx.x;
    const float* srcs[3] = {w1, w2, wf};
    const int    ns[3]   = {36, 144, 1960};
    for (int j = 0; j < 3; j++) {
        float m = 0.f;
        for (int i = t; i < ns[j]; i += 256) m = fmaxf(m, fabsf(srcs[j][i]));
        red[t] = m;
        __syncthreads();
        for (int s = 128; s > 0; s >>= 1) {
            if (t < s) red[t] = fmaxf(red[t], red[t + s]);
            __syncthreads();
        }
        if (t == 0) scales[j] = red[0];
        __syncthreads();
    }
    float s1 = scales[0], s2 = scales[1], sf = scales[2];

    if (t < 36) {   // conv1 transposed: t = k*4+ch
        int ch = t & 3, k = t >> 2;
        g_qw1t[t] = (float)qclip(w1[ch * 9 + k], s1) * s1;
    }
    if (t < 36) {   // conv2 [ocp][k][c]
        int ocp = t / 18, r = t % 18, k = r >> 1, c = r & 1;
        int oc = 2 * ocp + c;
        int packed = 0;
        #pragma unroll
        for (int ci = 0; ci < 4; ci++) {
            int q = qclip(w2[(oc * 4 + ci) * 9 + k], s2);
            packed |= (q & 0xFF) << (8 * ci);
        }
        g_w2p2[t] = packed;
    }
    for (int i = t; i < 528; i += 256) {
        if (i < 490) {
            int o = i / 49, j = i % 49;
            int packed = 0;
            #pragma unroll
            for (int ci = 0; ci < 4; ci++) {
                int q = qclip(wf[o * 196 + ci * 49 + j], sf);
                packed |= (q & 0xFF) << (8 * ci);
            }
            g_wfp[i] = packed;
        } else {
            g_wfp[i] = 0;   // pad so FC second dp4a can run unconditionally OOB-safe
        }
    }
    if (t == 0) { g_scales[0] = 2.f * s2; g_scales[1] = 2.f * sf; }
}

// ---- f32x2 packed helpers ----
typedef unsigned long long ull;
__device__ __forceinline__ ull pk2(float a, float b) {
    ull r; asm("mov.b64 %0, {%1, %2};" : "=l"(r) : "f"(a), "f"(b)); return r;
}
__device__ __forceinline__ ull dup2(float a) {
    ull r; asm("mov.b64 %0, {%1, %1};" : "=l"(r) : "f"(a)); return r;
}
__device__ __forceinline__ void ffma2(ull& d, ull a, ull b) {
    asm("fma.rn.f32x2 %0, %1, %2, %0;" : "+l"(d) : "l"(a), "l"(b));
}
__device__ __forceinline__ void unpk2(ull v, float& lo, float& hi) {
    asm("mov.b64 {%0, %1}, %2;" : "=f"(lo), "=f"(hi) : "l"(v));
}

__device__ __forceinline__ int quant2b(float v) {
    return max(__float2int_rn(fminf(v, 6.f) * 0.5f), 0);
}

// ---------------------------------------------------------------------------
// Warp-per-image fused kernel. Block = 4 independent images, no block syncs.
// ---------------------------------------------------------------------------
__global__ __launch_bounds__(128, 6)
void fused_kernel(const float* __restrict__ x, float* __restrict__ out, int B) {
    __shared__ __align__(16) float s_in[4][900];   // padded 30x30 per image
    __shared__ __align__(16) int   s_p1[4][256];   // padded 16x16 int8x4 acts
    __shared__ __align__(8)  int   s_p2[4][52];    // 7x7 int8x4 acts

    const int t    = threadIdx.x;
    const int lane = t & 31;
    const int w    = t >> 5;
    const int img  = blockIdx.x * 4 + w;
    if (img >= B) return;

    float* my_in = s_in[w];
    int*   my_p1 = s_p1[w];
    int*   my_p2 = s_p2[w];

    // ---- Phase A: zero pads + load input (per-warp, no block sync) ----
    {
        // zero whole p1 (2 int4 stores per lane)
        ((int4*)my_p1)[lane]      = make_int4(0, 0, 0, 0);
        ((int4*)my_p1)[lane + 32] = make_int4(0, 0, 0, 0);
        // border of 30x30: 116 cells
        for (int i = lane; i < 116; i += 32) {
            int r, c;
            if (i < 30)      { r = 0;      c = i;      }
            else if (i < 60) { r = 29;     c = i - 30; }
            else if (i < 88) { r = i - 59; c = 0;      }
            else             { r = i - 87; c = 29;     }
            my_in[r * 30 + c] = 0.f;
        }
        const float4* xv = (const float4*)(x + (size_t)img * 784);
        for (int idx = lane; idx < 196; idx += 32) {
            float4 v = xv[idx];
            int y = idx / 7, c0 = (idx % 7) * 4;
            float* dst = my_in + (y + 1) * 30 + c0 + 1;
            dst[0] = v.x; dst[1] = v.y; dst[2] = v.z; dst[3] = v.w;
        }
    }
    __syncwarp();

    // ---- Phase B: conv1 + pool + quant (packed f32x2 channel pairs) ----
    {
        ull w01[9], w23[9];
        #pragma unroll
        for (int k = 0; k < 9; k++) {
            float4 v = __ldg((const float4*)g_qw1t + k);
            w01[k] = pk2(v.x, v.y);
            w23[k] = pk2(v.z, v.w);
        }
        for (int p = lane; p < 196; p += 32) {
            int py = p / 14, px = p - py * 14;
            const float* bp = my_in + py * 60 + px * 2;
            ull a01[4] = {0, 0, 0, 0};
            ull a23[4] = {0, 0, 0, 0};
            #pragma unroll
            for (int row = 0; row < 4; row++) {
                float2 u = *(const float2*)(bp + 30 * row);
                float2 v = *(const float2*)(bp + 30 * row + 2);
                ull d0 = dup2(u.x), d1 = dup2(u.y), d2 = dup2(v.x), d3 = dup2(v.y);
                #pragma unroll
                for (int dy = 0; dy < 2; dy++) {
                    int kr = row - dy;
                    if (kr >= 0 && kr <= 2) {
                        ffma2(a01[dy * 2 + 0], d0, w01[kr * 3 + 0]);
                        ffma2(a01[dy * 2 + 0], d1, w01[kr * 3 + 1]);
                        ffma2(a01[dy * 2 + 0], d2, w01[kr * 3 + 2]);
                        ffma2(a01[dy * 2 + 1], d1, w01[kr * 3 + 0]);
                        ffma2(a01[dy * 2 + 1], d2, w01[kr * 3 + 1]);
                        ffma2(a01[dy * 2 + 1], d3, w01[kr * 3 + 2]);
                        ffma2(a23[dy * 2 + 0], d0, w23[kr * 3 + 0]);
                        ffma2(a23[dy * 2 + 0], d1, w23[kr * 3 + 1]);
                        ffma2(a23[dy * 2 + 0], d2, w23[kr * 3 + 2]);
                        ffma2(a23[dy * 2 + 1], d1, w23[kr * 3 + 0]);
                        ffma2(a23[dy * 2 + 1], d2, w23[kr * 3 + 1]);
                        ffma2(a23[dy * 2 + 1], d3, w23[kr * 3 + 2]);
                    }
                }
            }
            float m0 = -1e30f, m1 = -1e30f, m2 = -1e30f, m3 = -1e30f;
            #pragma unroll
            for (int wi = 0; wi < 4; wi++) {
                float c0, c1, c2, c3;
                unpk2(a01[wi], c0, c1);
                unpk2(a23[wi], c2, c3);
                m0 = fmaxf(m0, c0); m1 = fmaxf(m1, c1);
                m2 = fmaxf(m2, c2); m3 = fmaxf(m3, c3);
            }
            int q0 = quant2b(m0), q1 = quant2b(m1),
                q2 = quant2b(m2), q3 = quant2b(m3);
            my_p1[(py + 1) * 16 + px + 1] = q0 | (q1 << 8) | (q2 << 16) | (q3 << 24);
        }
    }
    __syncwarp();

    // ---- Phase C: conv2 via dp4a. lane parity = oc-pair (weights hoisted). ----
    {
        const float hs2 = __ldg(&g_scales[0]);
        const int ocp = lane & 1;
        int wq0[9], wq1[9];
        #pragma unroll
        for (int k = 0; k < 9; k++) {
            int2 wv = __ldg((const int2*)(g_w2p2 + ocp * 18) + k);
            wq0[k] = wv.x; wq1[k] = wv.y;
        }
        for (int it = lane; it < 98; it += 32) {
            int pix = it >> 1;
            int py = pix / 7, px = pix - py * 7;
            const int* bp = my_p1 + py * 32 + px * 2;
            int a[16];
            #pragma unroll
            for (int i = 0; i < 4; i++) {
                int2 u = *(const int2*)(bp + 16 * i);
                int2 v = *(const int2*)(bp + 16 * i + 2);
                a[4*i] = u.x; a[4*i+1] = u.y; a[4*i+2] = v.x; a[4*i+3] = v.y;
            }
            int m0 = -1000000, m1 = -1000000;
            #pragma unroll
            for (int dy = 0; dy < 2; dy++) {
                #pragma unroll
                for (int dx = 0; dx < 2; dx++) {
                    int s0 = 0, s1 = 0;
                    #pragma unroll
                    for (int ky = 0; ky < 3; ky++) {
                        #pragma unroll
                        for (int kx = 0; kx < 3; kx++) {
                            int av = a[(dy + ky) * 4 + dx + kx];
                            s0 = __dp4a(av, wq0[ky * 3 + kx], s0);
                            s1 = __dp4a(av, wq1[ky * 3 + kx], s1);
                        }
                    }
                    m0 = max(m0, s0); m1 = max(m1, s1);
                }
            }
            int q0 = quant2b(hs2 * (float)m0);
            int q1 = quant2b(hs2 * (float)m1);
            ((unsigned short*)my_p2)[pix * 2 + ocp] =
                (unsigned short)(q0 | (q1 << 8));
        }
    }
    __syncwarp();

    // ---- Phase D: FC 196->10, dp4a + REDUX.SUM, whole warp ----
    {
        const float hsf = __ldg(&g_scales[1]);
        int a0 = my_p2[lane];
        int a1 = (lane < 17) ? my_p2[32 + lane] : 0;   // acts zero-padded via predicate
        float acc = 0.f;
        #pragma unroll
        for (int o = 0; o < 10; o++) {
            const int* wrow = g_wfp + o * 49;
            int s = __dp4a(a0, __ldg(wrow + lane), 0);
            s = __dp4a(a1, __ldg(wrow + 32 + lane), s);  // g_wfp padded: OOB-safe
            int r = __reduce_add_sync(0xffffffffu, s);
            if (lane == o) acc = hsf * (float)r;
        }
        if (lane < 10) out[(size_t)img * 10 + lane] = acc;
    }
}

extern "C" void kernel_launch(void* const* d_in, const int* in_sizes, int n_in,
                              void* d_out, int out_size) {
    const float* x  = (const float*)d_in[0];
    const float* w1 = (const float*)d_in[1];
    const float* w2 = (const float*)d_in[2];
    const float* wf = (const float*)d_in[3];
    float* out = (float*)d_out;
    int B = in_sizes[0] / 784;

    prep_kernel<<<1, 256>>>(w1, w2, wf);
    fused_kernel<<<(B + 3) / 4, 128>>>(x, out, B);
}